// round 9
// baseline (speedup 1.0000x reference)
#include <cuda_runtime.h>
#include <cstdint>

#define MAXB 16
#define MAXN 24564
#define MAXC 81
#define CAP  1024      // per-(b,c) candidate shortlist capacity
#define KPC  50        // MAX_PER_CLASS
#define MAXTOT 200
#define THETA 0.98f    // shortlist score threshold ( > SCORE_THR=0.5 )
#define TH2   0.995f   // tier-1 selection threshold (classes != 0)
#define SELB  512      // phaseB tier-1 selection capacity (pow2)
#define SELC  512      // phaseC selection capacity (pow2)
#define NBIN  512
#define ATILE 64       // anchors per phaseA pipeline stage
#define ANIT  8        // tiles per phaseA block
#define BULKROWS 32    // rows of each tile loaded via cp.async.bulk (rest via cp.async)

typedef unsigned long long ull;

// ---------------- static device scratch ----------------
__device__ float4 g_boxes[MAXB * MAXN];
__device__ unsigned char g_mask[MAXB * MAXN];
__device__ ull g_cand[(size_t)MAXB * MAXC * CAP];
__device__ int g_candCnt[MAXB * MAXC];
__device__ float g_keptScore[MAXB * MAXC * KPC];
__device__ int   g_keptN[MAXB * MAXC * KPC];

__device__ __forceinline__ float iouf(float4 a, float4 b) {
    float iy1 = fmaxf(a.x, b.x);
    float ix1 = fmaxf(a.y, b.y);
    float iy2 = fminf(a.z, b.z);
    float ix2 = fminf(a.w, b.w);
    float inter = fmaxf(iy2 - iy1, 0.f) * fmaxf(ix2 - ix1, 0.f);
    float a0 = (a.z - a.x) * (a.w - a.y);
    float a1 = (b.z - b.x) * (b.w - b.y);
    return inter / (a0 + a1 - inter + 1e-8f);
}

__device__ __forceinline__ void bitonic_desc(ull* a, int P, int tid, int nthreads) {
    for (int k = 2; k <= P; k <<= 1) {
        for (int j = k >> 1; j > 0; j >>= 1) {
            for (int i = tid; i < P; i += nthreads) {
                int ixj = i ^ j;
                if (ixj > i) {
                    ull x = a[i], y = a[ixj];
                    if (((i & k) != 0) ? (x > y) : (x < y)) { a[i] = y; a[ixj] = x; }
                }
            }
            __syncthreads();
        }
    }
}

// warp-level bitonic sort of 128 ull keys, descending. lane holds v[r] = elem r*32+lane.
__device__ __forceinline__ void wsort128(ull v[4], int lane) {
    for (int k = 2; k <= 128; k <<= 1) {
        for (int j = k >> 1; j > 0; j >>= 1) {
            if (j >= 32) {
                int rj = j >> 5;                     // 1 or 2
                #pragma unroll
                for (int r = 0; r < 4; r++) {
                    if ((r & rj) == 0) {
                        int rh = r | rj;
                        int idx = r * 32 + lane;
                        bool dir = ((idx & k) == 0);  // descending segment
                        ull a = v[r], b = v[rh];
                        ull mx = a > b ? a : b;
                        ull mn = a > b ? b : a;
                        v[r]  = dir ? mx : mn;
                        v[rh] = dir ? mn : mx;
                    }
                }
            } else {
                #pragma unroll
                for (int r = 0; r < 4; r++) {
                    int idx = r * 32 + lane;
                    ull o = __shfl_xor_sync(0xffffffffu, v[r], j);
                    bool dir = ((idx & k) == 0);
                    bool lower = ((lane & j) == 0);
                    ull mx = v[r] > o ? v[r] : o;
                    ull mn = v[r] > o ? o : v[r];
                    v[r] = (dir == lower) ? mx : mn;
                }
            }
        }
    }
}

// ---- async-copy helpers ----
__device__ __forceinline__ uint32_t smem_u32(const void* p) {
    return (uint32_t)__cvta_generic_to_shared(p);
}
__device__ __forceinline__ void mbar_init(uint32_t a, uint32_t cnt) {
    asm volatile("mbarrier.init.shared.b64 [%0], %1;" :: "r"(a), "r"(cnt) : "memory");
}
__device__ __forceinline__ void mbar_expect_tx(uint32_t a, uint32_t bytes) {
    asm volatile("mbarrier.arrive.expect_tx.shared.b64 _, [%0], %1;"
                 :: "r"(a), "r"(bytes) : "memory");
}
__device__ __forceinline__ void bulk_g2s(uint32_t sdst, const void* gsrc,
                                         uint32_t bytes, uint32_t mbar) {
    asm volatile(
        "cp.async.bulk.shared::cluster.global.mbarrier::complete_tx::bytes "
        "[%0], [%1], %2, [%3];"
        :: "r"(sdst), "l"(gsrc), "r"(bytes), "r"(mbar) : "memory");
}
__device__ __forceinline__ void mbar_wait(uint32_t a, uint32_t parity) {
    asm volatile(
        "{\n\t.reg .pred p;\n\t"
        "W%=:\n\t"
        "mbarrier.try_wait.parity.acquire.cta.shared::cta.b64 p, [%0], %1, 0x989680;\n\t"
        "@!p bra W%=;\n\t}"
        :: "r"(a), "r"(parity) : "memory");
}
__device__ __forceinline__ void cp_async16(uint32_t saddr, const void* gaddr) {
    asm volatile("cp.async.cg.shared.global [%0], [%1], 16;" :: "r"(saddr), "l"(gaddr));
}
__device__ __forceinline__ void cp_commit() {
    asm volatile("cp.async.commit_group;");
}
template <int W> __device__ __forceinline__ void cp_wait() {
    asm volatile("cp.async.wait_group %0;" :: "n"(W));
}

// ---------------- Phase A v8: hybrid bulk+cp.async pipeline, 4 lanes/anchor ----
__global__ __launch_bounds__(256) void phaseA(
    const float* __restrict__ labels,   // (B,N,C)
    const float* __restrict__ deltas,   // (B,N,4)
    const float* __restrict__ priors,   // (N,4)
    int N, int C)
{
    __shared__ __align__(16) float sL[2][ATILE * MAXC];   // 2 x 20.7 KB
    __shared__ __align__(8) ull sBar[2];

    int tid = threadIdx.x;
    int b = blockIdx.y;
    int blk0 = blockIdx.x * (ATILE * ANIT);
    int nAll = min(ATILE * ANIT, N - blk0);
    if (nAll <= 0) return;
    int nt = (nAll + ATILE - 1) / ATILE;
    size_t bBase = (size_t)b * N;

    uint32_t bar[2] = { smem_u32(&sBar[0]), smem_u32(&sBar[1]) };
    if (tid == 0) { mbar_init(bar[0], 1); mbar_init(bar[1], 1); }
    asm volatile("fence.proxy.async.shared::cta;" ::: "memory");
    __syncthreads();

    const float* gt0 = labels + (bBase + blk0) * (size_t)C;
    bool aligned = ((((uintptr_t)gt0) & 15) == 0);

    // hybrid prefetch: rows [0,BULKROWS) via bulk engine, rest via cp.async (LSU)
    auto prefetch = [&](int t) {
        int naT = min(ATILE, nAll - t * ATILE);
        const float* gsrc = gt0 + (size_t)t * ATILE * C;
        float* sdst = sL[t & 1];
        if (aligned) {
            int bulkRows = min(naT, BULKROWS);
            uint32_t bulkBytes = (uint32_t)bulkRows * C * 4u;  // 324B rows: mult of 4... bulk needs 16B mult
            uint32_t bb = bulkBytes & ~15u;
            if (tid == 0) {
                mbar_expect_tx(bar[t & 1], bb);
                if (bb) bulk_g2s(smem_u32(sdst), gsrc, bb, bar[t & 1]);
            }
            // cp.async part: floats [bb/4, naT*C)
            int f0 = (int)(bb >> 2);
            int totF = naT * C;
            int rem = totF - f0;
            int nf4 = rem >> 2;
            uint32_t sb = smem_u32(sdst);
            for (int i = tid; i < nf4; i += 256)
                cp_async16(sb + (f0 + i * 4) * 4, gsrc + f0 + i * 4);
            for (int i = f0 + (nf4 << 2) + tid; i < totF; i += 256)
                sdst[i] = gsrc[i];      // scalar tail (rare)
        } else {
            if (tid == 0) mbar_expect_tx(bar[t & 1], 0);
            int totF = naT * C;
            for (int i = tid; i < totF; i += 256) sdst[i] = gsrc[i];
        }
        cp_commit();
    };

    prefetch(0);
    if (nt > 1) prefetch(1);

    // decode overlaps the first loads
    for (int i = tid; i < nAll; i += 256) {
        int n = blk0 + i;
        float4 pr = ((const float4*)priors)[n];
        float4 dd = ((const float4*)deltas)[bBase + n];
        float ph = pr.z - pr.x, pw = pr.w - pr.y;
        float pcy = pr.x + 0.5f * ph, pcx = pr.y + 0.5f * pw;
        float d0 = dd.x * 0.1f, d1 = dd.y * 0.1f;
        float d2 = dd.z * 0.2f, d3 = dd.w * 0.2f;
        float cy = d0 * ph + pcy, cx = d1 * pw + pcx;
        float h = expf(d2) * ph, w = expf(d3) * pw;
        float4 bx;
        bx.x = fminf(fmaxf(cy - h * 0.5f, 0.f), 1.f);
        bx.y = fminf(fmaxf(cx - w * 0.5f, 0.f), 1.f);
        bx.z = fminf(fmaxf(cy + h * 0.5f, 0.f), 1.f);
        bx.w = fminf(fmaxf(cx + w * 0.5f, 0.f), 1.f);
        g_boxes[bBase + n] = bx;
    }

    int a4 = tid >> 2;                 // anchor-in-tile 0..63
    int q  = tid & 3;                  // quarter within anchor
    int start = q * 20 + (q != 0);     // class range start: {0,21,41,61}
    int len   = (q == 0) ? 21 : 20;
    int laneBase = (tid & 31) & ~3;

    for (int t = 0; t < nt; t++) {
        if (t + 1 < nt) cp_wait<1>(); else cp_wait<0>();
        mbar_wait(bar[t & 1], (t >> 1) & 1);
        __syncthreads();               // make every thread's cp.async data visible to all

        const float* buf = sL[t & 1];
        int naT = min(ATILE, nAll - t * ATILE);
        bool valid = (a4 < naT);
        const float* row = buf + (valid ? a4 : 0) * C;

        float v0 = (q == 0) ? row[0] : -1e30f;
        float m = -1e30f;
        unsigned cb = 0;
        #pragma unroll
        for (int i = 0; i < 21; i++) {
            if (i < len) {
                int c = start + i;
                float v = row[c];
                m = fmaxf(m, (c == 0) ? -1e30f : v);
                if (v > THETA) cb |= (1u << i);
            }
        }
        m = fmaxf(m, __shfl_xor_sync(0xffffffffu, m, 1));
        m = fmaxf(m, __shfl_xor_sync(0xffffffffu, m, 2));
        v0 = __shfl_sync(0xffffffffu, v0, laneBase);
        bool mask = (m > v0);          // argmax != 0 (first-index tie-break)

        if (valid) {
            int n = blk0 + t * ATILE + a4;
            if (q == 0) g_mask[bBase + n] = (unsigned char)mask;
            if (mask && cb) {
                unsigned tail = 0xFFFFFFFFu - (unsigned)n;
                while (cb) {
                    int k = __ffs(cb) - 1; cb &= cb - 1;
                    int c = start + k;
                    float v = row[c];
                    int col = b * C + c;
                    int p = atomicAdd(&g_candCnt[col], 1);
                    if (p < CAP)
                        g_cand[(size_t)col * CAP + p] =
                            ((ull)__float_as_uint(v) << 32) | (ull)tail;
                }
            }
        }
        __syncthreads();               // buffer fully consumed
        if (t + 2 < nt) prefetch(t + 2);
    }
}

// warp-0 sequential greedy scan over a descending-sorted array. Returns kept.
__device__ __forceinline__ int nms_scan(
    const ull* arr, int n, const float4* candBox, int prefN,
    size_t bBase, int lane,
    float4* keptBox, float* keptS, int* keptNi)
{
    int kept = 0;
    for (int i = 0; i < n && kept < KPC; i++) {
        ull kk = arr[i];
        unsigned nn = 0xFFFFFFFFu - (unsigned)(kk & 0xFFFFFFFFull);
        float4 bb = (i < prefN) ? candBox[i] : g_boxes[bBase + nn];
        bool sup = false;
        for (int t = lane; t < kept; t += 32)
            if (iouf(keptBox[t], bb) > 0.5f) sup = true;
        if (__any_sync(0xffffffffu, sup)) continue;
        if (lane == 0) {
            keptBox[kept] = bb;
            keptS[kept] = __uint_as_float((unsigned)(kk >> 32));
            keptNi[kept] = (int)nn;
        }
        kept++;
        __syncwarp();
    }
    return kept;
}

// ---------------- Phase B: tiered sorted-scan greedy NMS ----------------
// Path W (m<=128): warp-0 register sort, no block barriers in the hot path.
// Path S (m<=512): block smem bitonic (class 0).
// Tier 2: full shortlist sort. Tier 3: exact greedy (never taken in practice).
__global__ __launch_bounds__(128) void phaseB(
    const float* __restrict__ labels, int B, int N, int C)
{
    int col = blockIdx.x;                 // b*C + c
    int b = col / C, c = col - b * C;
    int tid = threadIdx.x, lane = tid & 31, wid = tid >> 5;

    __shared__ ull keys[CAP];
    __shared__ ull sel[SELB];
    __shared__ float4 candBox[128];
    __shared__ float4 keptBox[KPC];
    __shared__ float keptS[KPC];
    __shared__ int keptNi[KPC];
    __shared__ int s_selCnt, s_kept, s_t2, s_t3;
    __shared__ ull s_wmax[4];
    __shared__ ull s_best;

    int rawCnt = g_candCnt[col];
    int cnt = min(rawCnt, CAP);
    size_t bBase = (size_t)b * N;
    const ull* gsrc = g_cand + (size_t)col * CAP;

    if (tid == 0) { s_selCnt = 0; s_t2 = 0; s_t3 = 0; s_kept = 0; }
    __syncthreads();

    // ---- tier-1 selection straight from global (c==0 takes everything) ----
    const ull T2 = (c == 0) ? 0ull : (((ull)__float_as_uint(TH2)) << 32);
    for (int i = tid; i < cnt; i += 128) {
        ull k = gsrc[i];
        if (k >= T2) {
            int p = atomicAdd(&s_selCnt, 1);
            if (p < SELB) sel[p] = k;
        }
    }
    __syncthreads();
    int selCnt = s_selCnt;
    int m = min(selCnt, SELB);

    if (selCnt <= 128) {
        // ---- path W: single-warp register sort + gather + scan ----
        if (wid == 0) {
            ull v[4];
            #pragma unroll
            for (int r = 0; r < 4; r++) {
                int i = r * 32 + lane;
                v[r] = (i < m) ? sel[i] : 0ull;
            }
            wsort128(v, lane);
            #pragma unroll
            for (int r = 0; r < 4; r++) sel[r * 32 + lane] = v[r];
            __syncwarp();
            #pragma unroll
            for (int r = 0; r < 4; r++) {
                int i = r * 32 + lane;
                if (i < m) {
                    unsigned nn = 0xFFFFFFFFu - (unsigned)(sel[i] & 0xFFFFFFFFull);
                    candBox[i] = g_boxes[bBase + nn];
                }
            }
            __syncwarp();
            int kept = nms_scan(sel, m, candBox, m, bBase, lane,
                                keptBox, keptS, keptNi);
            if (lane == 0) {
                s_kept = kept;
                s_t2 = (kept < KPC && m < cnt);
            }
        }
    } else if (selCnt <= SELB) {
        // ---- path S: block smem bitonic ----
        int P = 128; while (P < m) P <<= 1;
        for (int i = tid; i < P; i += 128)
            if (i >= m) sel[i] = 0ull;
        __syncthreads();
        bitonic_desc(sel, P, tid, 128);
        for (int i = tid; i < m && i < 128; i += 128) {
            unsigned nn = 0xFFFFFFFFu - (unsigned)(sel[i] & 0xFFFFFFFFull);
            candBox[i] = g_boxes[bBase + nn];
        }
        __syncthreads();
        if (wid == 0) {
            int kept = nms_scan(sel, m, candBox, min(m, 128), bBase, lane,
                                keptBox, keptS, keptNi);
            if (lane == 0) {
                s_kept = kept;
                s_t2 = (kept < KPC && m < cnt);
            }
        }
    } else {
        if (tid == 0) s_t2 = 1;              // selection overflow
    }
    __syncthreads();

    // ---- tier 2: full bitonic over entire shortlist (rare) ----
    if (s_t2) {
        for (int i = tid; i < cnt; i += 128) keys[i] = gsrc[i];
        int P = 1; while (P < cnt) P <<= 1;
        if (P < 2) P = 2;
        for (int i = tid; i < P; i += 128)
            if (i >= cnt) keys[i] = 0ull;
        __syncthreads();
        bitonic_desc(keys, P, tid, 128);
        for (int i = tid; i < cnt && i < 128; i += 128) {
            unsigned nn = 0xFFFFFFFFu - (unsigned)(keys[i] & 0xFFFFFFFFull);
            candBox[i] = g_boxes[bBase + nn];
        }
        __syncthreads();
        if (wid == 0) {
            int kept = nms_scan(keys, cnt, candBox, min(cnt, 128), bBase, lane,
                                keptBox, keptS, keptNi);
            if (lane == 0) s_kept = kept;
        }
        __syncthreads();
    }

    if (tid == 0) s_t3 = (rawCnt > CAP) || (s_kept < KPC);
    __syncthreads();

    // ---- tier 3: exact repeated-argmax greedy over all scores > 0.5 ----
    if (s_t3) {
        if (tid == 0) s_kept = 0;
        __syncthreads();
        for (int iter = 0; iter < KPC; iter++) {
            int kept = s_kept;
            ull best = 0ull;
            for (int n = tid; n < N; n += 128) {
                if (!g_mask[bBase + n]) continue;
                float s = labels[(bBase + n) * C + c];
                if (s <= 0.5f) continue;
                ull key = ((ull)__float_as_uint(s) << 32) |
                          (0xFFFFFFFFu - (unsigned)n);
                if (key <= best) continue;
                float4 bb = g_boxes[bBase + n];
                bool sup = false;
                for (int t = 0; t < kept && !sup; t++) {
                    if (keptNi[t] == n) sup = true;
                    else if (iouf(keptBox[t], bb) > 0.5f) sup = true;
                }
                if (!sup) best = key;
            }
            for (int off = 16; off; off >>= 1) {
                ull o = __shfl_xor_sync(0xffffffffu, best, off);
                if (o > best) best = o;
            }
            if (lane == 0) s_wmax[wid] = best;
            __syncthreads();
            if (wid == 0) {
                ull v = (lane < 4) ? s_wmax[lane] : 0ull;
                for (int off = 2; off; off >>= 1) {
                    ull o = __shfl_xor_sync(0xffffffffu, v, off);
                    if (o > v) v = o;
                }
                if (lane == 0) s_best = v;
            }
            __syncthreads();
            if (s_best == 0ull) break;
            if (tid == 0) {
                ull kk = s_best;
                unsigned nn = 0xFFFFFFFFu - (unsigned)(kk & 0xFFFFFFFFull);
                keptBox[s_kept] = g_boxes[bBase + nn];
                keptS[s_kept] = __uint_as_float((unsigned)(kk >> 32));
                keptNi[s_kept] = (int)nn;
                s_kept = s_kept + 1;
            }
            __syncthreads();
        }
        __syncthreads();
    }

    int kept = s_kept;
    for (int k = tid; k < KPC; k += 128) {
        g_keptScore[(size_t)col * KPC + k] = (k < kept) ? keptS[k] : 0.f;
        g_keptN   [(size_t)col * KPC + k] = (k < kept) ? keptNi[k] : 0;
    }
}

// ---------------- Phase C: histogram top-200 selection + small sort ----------------
__global__ __launch_bounds__(256) void phaseC(
    float* __restrict__ out, int B, int N, int C)
{
    int b = blockIdx.x;
    int M = C * KPC;                       // 4050
    __shared__ ull sk[4096];
    __shared__ ull sel[SELC];
    __shared__ int hist[NBIN];
    __shared__ int s_cnt, s_thr, s_fb;
    int tid = threadIdx.x;

    // reset shortlist counters for the next replay
    for (int i = tid; i < C; i += 256) g_candCnt[b * C + i] = 0;

    for (int i = tid; i < 4096; i += 256) {
        ull k = 0ull;
        if (i < M) {
            float s = g_keptScore[(size_t)b * M + i];
            k = ((ull)__float_as_uint(s) << 32) | (0xFFFFFFFFu - (unsigned)i);
        }
        sk[i] = k;
    }
    for (int i = tid; i < NBIN; i += 256) hist[i] = 0;
    if (tid == 0) { s_cnt = 0; s_thr = -1; s_fb = 0; }
    __syncthreads();

    const unsigned LOu = __float_as_uint(0.9975f);
    for (int i = tid; i < M; i += 256) {
        unsigned fb = (unsigned)(sk[i] >> 32);
        int d = (int)(fb - LOu);
        int bin = (d < 0) ? 0 : min(NBIN - 1, d >> 7);
        atomicAdd(&hist[bin], 1);
    }
    __syncthreads();

    for (int off = 1; off < NBIN; off <<= 1) {
        int v0 = hist[tid]       + ((tid + off < NBIN) ? hist[tid + off] : 0);
        int i1 = tid + 256;
        int v1 = hist[i1]        + ((i1 + off < NBIN) ? hist[i1 + off] : 0);
        __syncthreads();
        hist[tid] = v0; hist[i1] = v1;
        __syncthreads();
    }
    for (int t = tid; t < NBIN; t += 256)
        if (hist[t] >= MAXTOT && (t == NBIN - 1 || hist[t + 1] < MAXTOT)) s_thr = t;
    __syncthreads();
    int thr = s_thr;
    if (thr <= 0 || hist[thr] > SELC) { if (tid == 0) s_fb = 1; }
    __syncthreads();

    if (!s_fb) {
        for (int i = tid; i < M; i += 256) {
            unsigned fb = (unsigned)(sk[i] >> 32);
            int d = (int)(fb - LOu);
            int bin = (d < 0) ? 0 : min(NBIN - 1, d >> 7);
            if (bin >= thr) {
                int p = atomicAdd(&s_cnt, 1);
                if (p < SELC) sel[p] = sk[i];
            }
        }
        __syncthreads();
        int nsel = s_cnt;
        for (int i = tid; i < SELC; i += 256)
            if (i >= nsel) sel[i] = 0ull;
        __syncthreads();
        bitonic_desc(sel, SELC, tid, 256);
    } else {
        bitonic_desc(sk, 4096, tid, 256);
    }

    const ull* src = s_fb ? sk : sel;

    float* outBoxes   = out;
    float* outScores  = out + (size_t)B * MAXTOT * 4;
    float* outClasses = outScores + (size_t)B * MAXTOT;
    float* outCount   = outClasses + (size_t)B * MAXTOT;

    int validFlag = 0;
    if (tid < MAXTOT) {
        ull kk = src[tid];
        float s = __uint_as_float((unsigned)(kk >> 32));
        unsigned flat = 0xFFFFFFFFu - (unsigned)(kk & 0xFFFFFFFFull);
        float4 bx = make_float4(0.f, 0.f, 0.f, 0.f);
        float cls = 0.f;
        if (s > 0.f) {
            int n = g_keptN[(size_t)b * M + flat];
            bx = g_boxes[(size_t)b * N + n];
            cls = (float)(flat / KPC);
            validFlag = 1;
        }
        size_t o = (size_t)b * MAXTOT + tid;
        outBoxes[o * 4 + 0] = bx.x;
        outBoxes[o * 4 + 1] = bx.y;
        outBoxes[o * 4 + 2] = bx.z;
        outBoxes[o * 4 + 3] = bx.w;
        outScores[o]  = s;
        outClasses[o] = cls;
    }
    int vc = __syncthreads_count(validFlag);
    if (tid == 0) outCount[b] = (float)vc;
}

// ---------------- launch ----------------
extern "C" void kernel_launch(void* const* d_in, const int* in_sizes, int n_in,
                              void* d_out, int out_size) {
    const float* deltas = (const float*)d_in[0];   // pred_deltas (B,N,4)
    const float* labels = (const float*)d_in[1];   // pred_labels (B,N,C)
    const float* priors = (const float*)d_in[2];   // prior_boxes (N,4)

    int N = in_sizes[2] / 4;
    int B = in_sizes[0] / (4 * N);
    int C = in_sizes[1] / (B * N);

    dim3 gA((N + ATILE * ANIT - 1) / (ATILE * ANIT), B);
    phaseA<<<gA, 256>>>(labels, deltas, priors, N, C);
    phaseB<<<B * C, 128>>>(labels, B, N, C);
    phaseC<<<B, 256>>>((float*)d_out, B, N, C);
}

// round 10
// speedup vs baseline: 1.0272x; 1.0272x over previous
#include <cuda_runtime.h>
#include <cstdint>

#define MAXB 16
#define MAXN 24564
#define MAXC 81
#define CAP  1024      // per-(b,c) candidate shortlist capacity
#define KPC  50        // MAX_PER_CLASS
#define MAXTOT 200
#define THETA 0.98f    // shortlist score threshold ( > SCORE_THR=0.5 )
#define TH2   0.995f   // tier-1 selection threshold (classes != 0)
#define SELB  512      // selection capacity (pow2)
#define NBIN  512
#define ATILE 64       // anchors per phaseA pipeline stage
#define ANIT  8        // tiles per phaseA block

typedef unsigned long long ull;

// ---------------- static device scratch ----------------
__device__ float4 g_boxes[MAXB * MAXN];
__device__ unsigned char g_mask[MAXB * MAXN];
__device__ ull g_cand[(size_t)MAXB * MAXC * CAP];
__device__ int g_candCnt[MAXB * MAXC];
__device__ float g_keptScore[MAXB * MAXC * KPC];
__device__ int   g_keptN[MAXB * MAXC * KPC];
__device__ int   g_done[MAXB];          // zero-initialized at module load

__device__ __forceinline__ float iouf(float4 a, float4 b) {
    float iy1 = fmaxf(a.x, b.x);
    float ix1 = fmaxf(a.y, b.y);
    float iy2 = fminf(a.z, b.z);
    float ix2 = fminf(a.w, b.w);
    float inter = fmaxf(iy2 - iy1, 0.f) * fmaxf(ix2 - ix1, 0.f);
    float a0 = (a.z - a.x) * (a.w - a.y);
    float a1 = (b.z - b.x) * (b.w - b.y);
    return inter / (a0 + a1 - inter + 1e-8f);
}

__device__ __forceinline__ void bitonic_desc(ull* a, int P, int tid, int nthreads) {
    for (int k = 2; k <= P; k <<= 1) {
        for (int j = k >> 1; j > 0; j >>= 1) {
            for (int i = tid; i < P; i += nthreads) {
                int ixj = i ^ j;
                if (ixj > i) {
                    ull x = a[i], y = a[ixj];
                    if (((i & k) != 0) ? (x > y) : (x < y)) { a[i] = y; a[ixj] = x; }
                }
            }
            __syncthreads();
        }
    }
}

// warp-level bitonic sort of 128 ull keys, descending. lane holds v[r] = elem r*32+lane.
__device__ __forceinline__ void wsort128(ull v[4], int lane) {
    for (int k = 2; k <= 128; k <<= 1) {
        for (int j = k >> 1; j > 0; j >>= 1) {
            if (j >= 32) {
                int rj = j >> 5;
                #pragma unroll
                for (int r = 0; r < 4; r++) {
                    if ((r & rj) == 0) {
                        int rh = r | rj;
                        int idx = r * 32 + lane;
                        bool dir = ((idx & k) == 0);
                        ull a = v[r], b = v[rh];
                        ull mx = a > b ? a : b;
                        ull mn = a > b ? b : a;
                        v[r]  = dir ? mx : mn;
                        v[rh] = dir ? mn : mx;
                    }
                }
            } else {
                #pragma unroll
                for (int r = 0; r < 4; r++) {
                    int idx = r * 32 + lane;
                    ull o = __shfl_xor_sync(0xffffffffu, v[r], j);
                    bool dir = ((idx & k) == 0);
                    bool lower = ((lane & j) == 0);
                    ull mx = v[r] > o ? v[r] : o;
                    ull mn = v[r] > o ? o : v[r];
                    v[r] = (dir == lower) ? mx : mn;
                }
            }
        }
    }
}

// ---- async-copy helpers ----
__device__ __forceinline__ uint32_t smem_u32(const void* p) {
    return (uint32_t)__cvta_generic_to_shared(p);
}
__device__ __forceinline__ void mbar_init(uint32_t a, uint32_t cnt) {
    asm volatile("mbarrier.init.shared.b64 [%0], %1;" :: "r"(a), "r"(cnt) : "memory");
}
__device__ __forceinline__ void mbar_expect_tx(uint32_t a, uint32_t bytes) {
    asm volatile("mbarrier.arrive.expect_tx.shared.b64 _, [%0], %1;"
                 :: "r"(a), "r"(bytes) : "memory");
}
__device__ __forceinline__ void bulk_g2s(uint32_t sdst, const void* gsrc,
                                         uint32_t bytes, uint32_t mbar) {
    asm volatile(
        "cp.async.bulk.shared::cluster.global.mbarrier::complete_tx::bytes "
        "[%0], [%1], %2, [%3];"
        :: "r"(sdst), "l"(gsrc), "r"(bytes), "r"(mbar) : "memory");
}
__device__ __forceinline__ void mbar_wait(uint32_t a, uint32_t parity) {
    asm volatile(
        "{\n\t.reg .pred p;\n\t"
        "W%=:\n\t"
        "mbarrier.try_wait.parity.acquire.cta.shared::cta.b64 p, [%0], %1, 0x989680;\n\t"
        "@!p bra W%=;\n\t}"
        :: "r"(a), "r"(parity) : "memory");
}

// ---------------- Phase A (R8 version): bulk-copy pipeline, 4 lanes/anchor ------
__global__ __launch_bounds__(256) void phaseA(
    const float* __restrict__ labels,   // (B,N,C)
    const float* __restrict__ deltas,   // (B,N,4)
    const float* __restrict__ priors,   // (N,4)
    int N, int C)
{
    __shared__ __align__(16) float sL[2][ATILE * MAXC];   // 2 x 20.7 KB
    __shared__ __align__(8) ull sBar[2];

    int tid = threadIdx.x;
    int b = blockIdx.y;
    int blk0 = blockIdx.x * (ATILE * ANIT);
    int nAll = min(ATILE * ANIT, N - blk0);
    if (nAll <= 0) return;
    int nt = (nAll + ATILE - 1) / ATILE;
    size_t bBase = (size_t)b * N;

    // --- decode all anchors of this block (independent of labels) ---
    for (int i = tid; i < nAll; i += 256) {
        int n = blk0 + i;
        float4 pr = ((const float4*)priors)[n];
        float4 dd = ((const float4*)deltas)[bBase + n];
        float ph = pr.z - pr.x, pw = pr.w - pr.y;
        float pcy = pr.x + 0.5f * ph, pcx = pr.y + 0.5f * pw;
        float d0 = dd.x * 0.1f, d1 = dd.y * 0.1f;
        float d2 = dd.z * 0.2f, d3 = dd.w * 0.2f;
        float cy = d0 * ph + pcy, cx = d1 * pw + pcx;
        float h = expf(d2) * ph, w = expf(d3) * pw;
        float4 bx;
        bx.x = fminf(fmaxf(cy - h * 0.5f, 0.f), 1.f);
        bx.y = fminf(fmaxf(cx - w * 0.5f, 0.f), 1.f);
        bx.z = fminf(fmaxf(cy + h * 0.5f, 0.f), 1.f);
        bx.w = fminf(fmaxf(cx + w * 0.5f, 0.f), 1.f);
        g_boxes[bBase + n] = bx;
    }

    uint32_t bar[2] = { smem_u32(&sBar[0]), smem_u32(&sBar[1]) };
    if (tid == 0) { mbar_init(bar[0], 1); mbar_init(bar[1], 1); }
    asm volatile("fence.proxy.async.shared::cta;" ::: "memory");
    __syncthreads();

    const float* gt0 = labels + (bBase + blk0) * (size_t)C;

    auto prefetch = [&](int t) {
        int naT = min(ATILE, nAll - t * ATILE);
        uint32_t bytes = (uint32_t)naT * C * 4u;
        const float* gsrc = gt0 + (size_t)t * ATILE * C;
        float* sdst = sL[t & 1];
        bool al = ((((uintptr_t)gsrc) & 15) == 0);
        uint32_t bb = al ? (bytes & ~15u) : 0u;
        if (tid == 0) {
            mbar_expect_tx(bar[t & 1], bb);
            if (bb) bulk_g2s(smem_u32(sdst), gsrc, bb, bar[t & 1]);
        }
        int remF = (int)((bytes - bb) >> 2);
        int baseF = (int)(bb >> 2);
        for (int i = tid; i < remF; i += 256) sdst[baseF + i] = gsrc[baseF + i];
    };

    prefetch(0);
    if (nt > 1) prefetch(1);
    __syncthreads();   // orders any scalar tail stores before first consumption

    int a4 = tid >> 2;                 // anchor-in-tile 0..63
    int q  = tid & 3;                  // quarter within anchor
    int start = q * 20 + (q != 0);     // class range start: {0,21,41,61}
    int len   = (q == 0) ? 21 : 20;
    int laneBase = (tid & 31) & ~3;

    for (int t = 0; t < nt; t++) {
        mbar_wait(bar[t & 1], (t >> 1) & 1);

        const float* buf = sL[t & 1];
        int naT = min(ATILE, nAll - t * ATILE);
        bool valid = (a4 < naT);
        const float* row = buf + (valid ? a4 : 0) * C;

        float v0 = (q == 0) ? row[0] : -1e30f;
        float m = -1e30f;
        unsigned cb = 0;
        #pragma unroll
        for (int i = 0; i < 21; i++) {
            if (i < len) {
                int c = start + i;
                float v = row[c];
                m = fmaxf(m, (c == 0) ? -1e30f : v);
                if (v > THETA) cb |= (1u << i);
            }
        }
        m = fmaxf(m, __shfl_xor_sync(0xffffffffu, m, 1));
        m = fmaxf(m, __shfl_xor_sync(0xffffffffu, m, 2));
        v0 = __shfl_sync(0xffffffffu, v0, laneBase);
        bool mask = (m > v0);          // argmax != 0 (first-index tie-break)

        if (valid) {
            int n = blk0 + t * ATILE + a4;
            if (q == 0) g_mask[bBase + n] = (unsigned char)mask;
            if (mask && cb) {
                unsigned tail = 0xFFFFFFFFu - (unsigned)n;
                while (cb) {
                    int k = __ffs(cb) - 1; cb &= cb - 1;
                    int c = start + k;
                    float v = row[c];
                    int col = b * C + c;
                    int p = atomicAdd(&g_candCnt[col], 1);
                    if (p < CAP)
                        g_cand[(size_t)col * CAP + p] =
                            ((ull)__float_as_uint(v) << 32) | (ull)tail;
                }
            }
        }
        __syncthreads();
        if (t + 2 < nt) prefetch(t + 2);
    }
}

// warp-0 sequential greedy scan over a descending-sorted array. Returns kept.
__device__ __forceinline__ int nms_scan(
    const ull* arr, int n, const float4* candBox, int prefN,
    size_t bBase, int lane,
    float4* keptBox, float* keptS, int* keptNi)
{
    int kept = 0;
    for (int i = 0; i < n && kept < KPC; i++) {
        ull kk = arr[i];
        unsigned nn = 0xFFFFFFFFu - (unsigned)(kk & 0xFFFFFFFFull);
        float4 bb = (i < prefN) ? candBox[i] : g_boxes[bBase + nn];
        bool sup = false;
        for (int t = lane; t < kept; t += 32)
            if (iouf(keptBox[t], bb) > 0.5f) sup = true;
        if (__any_sync(0xffffffffu, sup)) continue;
        if (lane == 0) {
            keptBox[kept] = bb;
            keptS[kept] = __uint_as_float((unsigned)(kk >> 32));
            keptNi[kept] = (int)nn;
        }
        kept++;
        __syncwarp();
    }
    return kept;
}

// ---------------- Phase B (+ fused per-batch top-200 merge) ----------------
__global__ __launch_bounds__(128) void phaseB(
    const float* __restrict__ labels, float* __restrict__ out,
    int B, int N, int C)
{
    int col = blockIdx.x;                 // b*C + c
    int b = col / C, c = col - b * C;
    int tid = threadIdx.x, lane = tid & 31, wid = tid >> 5;

    __shared__ ull keys[CAP];
    __shared__ ull sel[SELB];
    __shared__ float4 candBox[128];
    __shared__ float4 keptBox[KPC];
    __shared__ float keptS[KPC];
    __shared__ int keptNi[KPC];
    __shared__ int s_selCnt, s_kept, s_t2, s_t3, s_elect;
    __shared__ ull s_wmax[4];
    __shared__ ull s_best;

    int rawCnt = g_candCnt[col];
    __syncthreads();                      // all reads of counter done
    if (tid == 0) g_candCnt[col] = 0;     // reset for next replay
    int cnt = min(rawCnt, CAP);
    size_t bBase = (size_t)b * N;
    const ull* gsrc = g_cand + (size_t)col * CAP;

    if (tid == 0) { s_selCnt = 0; s_t2 = 0; s_t3 = 0; s_kept = 0; }
    __syncthreads();

    // ---- tier-1 selection straight from global (c==0 takes everything) ----
    const ull T2 = (c == 0) ? 0ull : (((ull)__float_as_uint(TH2)) << 32);
    for (int i = tid; i < cnt; i += 128) {
        ull k = gsrc[i];
        if (k >= T2) {
            int p = atomicAdd(&s_selCnt, 1);
            if (p < SELB) sel[p] = k;
        }
    }
    __syncthreads();
    int selCnt = s_selCnt;
    int m = min(selCnt, SELB);

    if (selCnt <= 128) {
        // ---- path W: single-warp register sort + gather + scan ----
        if (wid == 0) {
            ull v[4];
            #pragma unroll
            for (int r = 0; r < 4; r++) {
                int i = r * 32 + lane;
                v[r] = (i < m) ? sel[i] : 0ull;
            }
            wsort128(v, lane);
            #pragma unroll
            for (int r = 0; r < 4; r++) sel[r * 32 + lane] = v[r];
            __syncwarp();
            #pragma unroll
            for (int r = 0; r < 4; r++) {
                int i = r * 32 + lane;
                if (i < m) {
                    unsigned nn = 0xFFFFFFFFu - (unsigned)(sel[i] & 0xFFFFFFFFull);
                    candBox[i] = g_boxes[bBase + nn];
                }
            }
            __syncwarp();
            int kept = nms_scan(sel, m, candBox, m, bBase, lane,
                                keptBox, keptS, keptNi);
            if (lane == 0) {
                s_kept = kept;
                s_t2 = (kept < KPC && m < cnt);
            }
        }
    } else if (selCnt <= SELB) {
        // ---- path S: block smem bitonic (class 0) ----
        int P = 128; while (P < m) P <<= 1;
        for (int i = tid; i < P; i += 128)
            if (i >= m) sel[i] = 0ull;
        __syncthreads();
        bitonic_desc(sel, P, tid, 128);
        for (int i = tid; i < m && i < 128; i += 128) {
            unsigned nn = 0xFFFFFFFFu - (unsigned)(sel[i] & 0xFFFFFFFFull);
            candBox[i] = g_boxes[bBase + nn];
        }
        __syncthreads();
        if (wid == 0) {
            int kept = nms_scan(sel, m, candBox, min(m, 128), bBase, lane,
                                keptBox, keptS, keptNi);
            if (lane == 0) {
                s_kept = kept;
                s_t2 = (kept < KPC && m < cnt);
            }
        }
    } else {
        if (tid == 0) s_t2 = 1;
    }
    __syncthreads();

    // ---- tier 2: full bitonic over entire shortlist (rare) ----
    if (s_t2) {
        for (int i = tid; i < cnt; i += 128) keys[i] = gsrc[i];
        int P = 1; while (P < cnt) P <<= 1;
        if (P < 2) P = 2;
        for (int i = tid; i < P; i += 128)
            if (i >= cnt) keys[i] = 0ull;
        __syncthreads();
        bitonic_desc(keys, P, tid, 128);
        for (int i = tid; i < cnt && i < 128; i += 128) {
            unsigned nn = 0xFFFFFFFFu - (unsigned)(keys[i] & 0xFFFFFFFFull);
            candBox[i] = g_boxes[bBase + nn];
        }
        __syncthreads();
        if (wid == 0) {
            int kept = nms_scan(keys, cnt, candBox, min(cnt, 128), bBase, lane,
                                keptBox, keptS, keptNi);
            if (lane == 0) s_kept = kept;
        }
        __syncthreads();
    }

    if (tid == 0) s_t3 = (rawCnt > CAP) || (s_kept < KPC);
    __syncthreads();

    // ---- tier 3: exact repeated-argmax greedy over all scores > 0.5 ----
    if (s_t3) {
        if (tid == 0) s_kept = 0;
        __syncthreads();
        for (int iter = 0; iter < KPC; iter++) {
            int kept = s_kept;
            ull best = 0ull;
            for (int n = tid; n < N; n += 128) {
                if (!g_mask[bBase + n]) continue;
                float s = labels[(bBase + n) * C + c];
                if (s <= 0.5f) continue;
                ull key = ((ull)__float_as_uint(s) << 32) |
                          (0xFFFFFFFFu - (unsigned)n);
                if (key <= best) continue;
                float4 bb = g_boxes[bBase + n];
                bool sup = false;
                for (int t = 0; t < kept && !sup; t++) {
                    if (keptNi[t] == n) sup = true;
                    else if (iouf(keptBox[t], bb) > 0.5f) sup = true;
                }
                if (!sup) best = key;
            }
            for (int off = 16; off; off >>= 1) {
                ull o = __shfl_xor_sync(0xffffffffu, best, off);
                if (o > best) best = o;
            }
            if (lane == 0) s_wmax[wid] = best;
            __syncthreads();
            if (wid == 0) {
                ull v = (lane < 4) ? s_wmax[lane] : 0ull;
                for (int off = 2; off; off >>= 1) {
                    ull o = __shfl_xor_sync(0xffffffffu, v, off);
                    if (o > v) v = o;
                }
                if (lane == 0) s_best = v;
            }
            __syncthreads();
            if (s_best == 0ull) break;
            if (tid == 0) {
                ull kk = s_best;
                unsigned nn = 0xFFFFFFFFu - (unsigned)(kk & 0xFFFFFFFFull);
                keptBox[s_kept] = g_boxes[bBase + nn];
                keptS[s_kept] = __uint_as_float((unsigned)(kk >> 32));
                keptNi[s_kept] = (int)nn;
                s_kept = s_kept + 1;
            }
            __syncthreads();
        }
        __syncthreads();
    }

    int kept = s_kept;
    for (int k = tid; k < KPC; k += 128) {
        g_keptScore[(size_t)col * KPC + k] = (k < kept) ? keptS[k] : 0.f;
        g_keptN   [(size_t)col * KPC + k] = (k < kept) ? keptNi[k] : 0;
    }

    // ================= fused per-batch merge (last block of batch b) ==========
    __threadfence();
    __syncthreads();
    if (tid == 0) {
        int old = atomicAdd(&g_done[b], 1);
        s_elect = (old == C - 1);
        if (s_elect) g_done[b] = 0;          // reset for next replay
    }
    __syncthreads();
    if (!s_elect) return;
    __threadfence();                         // acquire: see all blocks' results

    int M = C * KPC;                          // 4050
    const float* ks = g_keptScore + (size_t)b * M;
    int* hist = (int*)keys;                   // reuse dead smem (needs 2 KB)
    __shared__ int s_cnt2, s_thr, s_fb, s_vc;

    for (int i = tid; i < NBIN; i += 128) hist[i] = 0;
    if (tid == 0) { s_cnt2 = 0; s_thr = -1; s_fb = 0; s_vc = 0; }
    __syncthreads();

    const unsigned LOu = __float_as_uint(0.9975f);
    for (int i = tid; i < M; i += 128) {
        unsigned fb = __float_as_uint(ks[i]);
        int d = (int)(fb - LOu);
        int bin = (d < 0) ? 0 : min(NBIN - 1, d >> 7);
        atomicAdd(&hist[bin], 1);
    }
    __syncthreads();

    // inclusive suffix-sum (Hillis-Steele), 4 bins per thread
    for (int off = 1; off < NBIN; off <<= 1) {
        int v[4];
        #pragma unroll
        for (int r = 0; r < 4; r++) {
            int i = tid + 128 * r;
            v[r] = hist[i] + ((i + off < NBIN) ? hist[i + off] : 0);
        }
        __syncthreads();
        #pragma unroll
        for (int r = 0; r < 4; r++) hist[tid + 128 * r] = v[r];
        __syncthreads();
    }
    for (int t = tid; t < NBIN; t += 128)
        if (hist[t] >= MAXTOT && (t == NBIN - 1 || hist[t + 1] < MAXTOT)) s_thr = t;
    __syncthreads();
    int thr = s_thr;
    if (tid == 0 && (thr <= 0 || hist[thr] > SELB)) s_fb = 1;
    __syncthreads();

    if (!s_fb) {
        for (int i = tid; i < M; i += 128) {
            unsigned fb = __float_as_uint(ks[i]);
            int d = (int)(fb - LOu);
            int bin = (d < 0) ? 0 : min(NBIN - 1, d >> 7);
            if (bin >= thr) {
                int p = atomicAdd(&s_cnt2, 1);
                if (p < SELB)
                    sel[p] = ((ull)fb << 32) | (0xFFFFFFFFu - (unsigned)i);
            }
        }
        __syncthreads();
        int nsel = s_cnt2;
        for (int i = tid; i < SELB; i += 128)
            if (i >= nsel) sel[i] = 0ull;
        __syncthreads();
        bitonic_desc(sel, SELB, tid, 128);
    } else {
        // exact fallback: 200 sequential argmax passes over global (never taken)
        __shared__ ull s_last;
        if (tid == 0) s_last = ~0ull;
        __syncthreads();
        for (int it = 0; it < MAXTOT; it++) {
            ull lim = s_last;
            ull best = 0ull;
            for (int i = tid; i < M; i += 128) {
                ull key = ((ull)__float_as_uint(ks[i]) << 32) |
                          (0xFFFFFFFFu - (unsigned)i);
                if (key < lim && key > best) best = key;
            }
            for (int off = 16; off; off >>= 1) {
                ull o = __shfl_xor_sync(0xffffffffu, best, off);
                if (o > best) best = o;
            }
            if (lane == 0) s_wmax[wid] = best;
            __syncthreads();
            if (wid == 0) {
                ull v = (lane < 4) ? s_wmax[lane] : 0ull;
                for (int off = 2; off; off >>= 1) {
                    ull o = __shfl_xor_sync(0xffffffffu, v, off);
                    if (o > v) v = o;
                }
                if (lane == 0) { sel[it] = v; s_last = v; }
            }
            __syncthreads();
        }
    }

    float* outBoxes   = out;
    float* outScores  = out + (size_t)B * MAXTOT * 4;
    float* outClasses = outScores + (size_t)B * MAXTOT;
    float* outCount   = outClasses + (size_t)B * MAXTOT;

    for (int i = tid; i < MAXTOT; i += 128) {
        ull kk = sel[i];
        float s = __uint_as_float((unsigned)(kk >> 32));
        unsigned flat = 0xFFFFFFFFu - (unsigned)(kk & 0xFFFFFFFFull);
        float4 bx = make_float4(0.f, 0.f, 0.f, 0.f);
        float cls = 0.f;
        if (s > 0.f) {
            int n = g_keptN[(size_t)b * M + flat];
            bx = g_boxes[bBase + n];
            cls = (float)(flat / KPC);
            atomicAdd(&s_vc, 1);
        }
        size_t o = (size_t)b * MAXTOT + i;
        outBoxes[o * 4 + 0] = bx.x;
        outBoxes[o * 4 + 1] = bx.y;
        outBoxes[o * 4 + 2] = bx.z;
        outBoxes[o * 4 + 3] = bx.w;
        outScores[o]  = s;
        outClasses[o] = cls;
    }
    __syncthreads();
    if (tid == 0) outCount[b] = (float)s_vc;
}

// ---------------- launch ----------------
extern "C" void kernel_launch(void* const* d_in, const int* in_sizes, int n_in,
                              void* d_out, int out_size) {
    const float* deltas = (const float*)d_in[0];   // pred_deltas (B,N,4)
    const float* labels = (const float*)d_in[1];   // pred_labels (B,N,C)
    const float* priors = (const float*)d_in[2];   // prior_boxes (N,4)

    int N = in_sizes[2] / 4;
    int B = in_sizes[0] / (4 * N);
    int C = in_sizes[1] / (B * N);

    dim3 gA((N + ATILE * ANIT - 1) / (ATILE * ANIT), B);
    phaseA<<<gA, 256>>>(labels, deltas, priors, N, C);
    phaseB<<<B * C, 128>>>(labels, (float*)d_out, B, N, C);
}

// round 11
// speedup vs baseline: 1.3287x; 1.2935x over previous
#include <cuda_runtime.h>
#include <cstdint>

#define MAXB 16
#define MAXN 24564
#define MAXC 81
#define CAP  1024      // per-(b,c) candidate shortlist capacity
#define KPC  50        // MAX_PER_CLASS
#define MAXTOT 200
#define TH_C0 0.98f    // shortlist threshold, class 0
#define TH_CX 0.995f   // shortlist threshold, classes != 0
#define SELB  512
#define NBIN  512
#define ATILE 64       // anchors per phaseA pipeline stage
#define ANIT  8        // tiles per phaseA block
#define GATHN 96       // boxes prefetched to smem per class

typedef unsigned long long ull;

// ---------------- static device scratch ----------------
__device__ float4 g_boxes[MAXB * MAXN];
__device__ unsigned char g_mask[MAXB * MAXN];
__device__ ull g_cand[(size_t)MAXB * MAXC * CAP];
__device__ int g_candCnt[MAXB * MAXC];
__device__ float g_keptScore[MAXB * MAXC * KPC];
__device__ int   g_keptN[MAXB * MAXC * KPC];
__device__ int   g_done[MAXB];          // zero-initialized at module load

__device__ __forceinline__ float iouf(float4 a, float4 b) {
    float iy1 = fmaxf(a.x, b.x);
    float ix1 = fmaxf(a.y, b.y);
    float iy2 = fminf(a.z, b.z);
    float ix2 = fminf(a.w, b.w);
    float inter = fmaxf(iy2 - iy1, 0.f) * fmaxf(ix2 - ix1, 0.f);
    float a0 = (a.z - a.x) * (a.w - a.y);
    float a1 = (b.z - b.x) * (b.w - b.y);
    return inter / (a0 + a1 - inter + 1e-8f);
}

__device__ __forceinline__ void bitonic_desc(ull* a, int P, int tid, int nthreads) {
    for (int k = 2; k <= P; k <<= 1) {
        for (int j = k >> 1; j > 0; j >>= 1) {
            for (int i = tid; i < P; i += nthreads) {
                int ixj = i ^ j;
                if (ixj > i) {
                    ull x = a[i], y = a[ixj];
                    if (((i & k) != 0) ? (x > y) : (x < y)) { a[i] = y; a[ixj] = x; }
                }
            }
            __syncthreads();
        }
    }
}

// ---- register bitonic stages (RJ compile-time -> no dynamic reg indexing) ----
template<int R, int RJ>
__device__ __forceinline__ void regstage(ull* v, int lane, int k) {
    #pragma unroll
    for (int r = 0; r < R; r++) {
        if ((r & RJ) == 0) {
            int rh = r | RJ;
            int idx = r * 32 + lane;
            bool dir = ((idx & k) == 0);
            ull a = v[r], b = v[rh];
            ull mx = a > b ? a : b;
            ull mn = a > b ? b : a;
            v[r]  = dir ? mx : mn;
            v[rh] = dir ? mn : mx;
        }
    }
}

// warp bitonic sort of n=R*32 ull keys descending; lane holds v[r]=elem r*32+lane
template<int R>
__device__ __forceinline__ void wsortN(ull* v, int lane) {
    const int n = R * 32;
    for (int k = 2; k <= n; k <<= 1) {
        for (int j = k >> 1; j > 0; j >>= 1) {
            if (j >= 32) {
                switch (j >> 5) {
                    case 1: regstage<R, 1>(v, lane, k); break;
                    case 2: regstage<R, 2>(v, lane, k); break;
                    case 4: regstage<R, 4>(v, lane, k); break;
                    case 8: regstage<R, 8>(v, lane, k); break;
                }
            } else {
                #pragma unroll
                for (int r = 0; r < R; r++) {
                    int idx = r * 32 + lane;
                    ull o = __shfl_xor_sync(0xffffffffu, v[r], j);
                    bool dir = ((idx & k) == 0);
                    bool lower = ((lane & j) == 0);
                    ull mx = v[r] > o ? v[r] : o;
                    ull mn = v[r] > o ? o : v[r];
                    v[r] = (dir == lower) ? mx : mn;
                }
            }
        }
    }
}

// ---- async-copy helpers ----
__device__ __forceinline__ uint32_t smem_u32(const void* p) {
    return (uint32_t)__cvta_generic_to_shared(p);
}
__device__ __forceinline__ void mbar_init(uint32_t a, uint32_t cnt) {
    asm volatile("mbarrier.init.shared.b64 [%0], %1;" :: "r"(a), "r"(cnt) : "memory");
}
__device__ __forceinline__ void mbar_expect_tx(uint32_t a, uint32_t bytes) {
    asm volatile("mbarrier.arrive.expect_tx.shared.b64 _, [%0], %1;"
                 :: "r"(a), "r"(bytes) : "memory");
}
__device__ __forceinline__ void bulk_g2s(uint32_t sdst, const void* gsrc,
                                         uint32_t bytes, uint32_t mbar) {
    asm volatile(
        "cp.async.bulk.shared::cluster.global.mbarrier::complete_tx::bytes "
        "[%0], [%1], %2, [%3];"
        :: "r"(sdst), "l"(gsrc), "r"(bytes), "r"(mbar) : "memory");
}
__device__ __forceinline__ void mbar_wait(uint32_t a, uint32_t parity) {
    asm volatile(
        "{\n\t.reg .pred p;\n\t"
        "W%=:\n\t"
        "mbarrier.try_wait.parity.acquire.cta.shared::cta.b64 p, [%0], %1, 0x989680;\n\t"
        "@!p bra W%=;\n\t}"
        :: "r"(a), "r"(parity) : "memory");
}

// ---------------- Phase A: bulk-copy pipeline, 4 lanes per anchor --------------
__global__ __launch_bounds__(256) void phaseA(
    const float* __restrict__ labels,   // (B,N,C)
    const float* __restrict__ deltas,   // (B,N,4)
    const float* __restrict__ priors,   // (N,4)
    int N, int C)
{
    __shared__ __align__(16) float sL[2][ATILE * MAXC];   // 2 x 20.7 KB
    __shared__ __align__(8) ull sBar[2];

    int tid = threadIdx.x;
    int b = blockIdx.y;
    int blk0 = blockIdx.x * (ATILE * ANIT);
    int nAll = min(ATILE * ANIT, N - blk0);
    if (nAll <= 0) return;
    int nt = (nAll + ATILE - 1) / ATILE;
    size_t bBase = (size_t)b * N;

    // --- decode all anchors of this block (independent of labels) ---
    for (int i = tid; i < nAll; i += 256) {
        int n = blk0 + i;
        float4 pr = ((const float4*)priors)[n];
        float4 dd = ((const float4*)deltas)[bBase + n];
        float ph = pr.z - pr.x, pw = pr.w - pr.y;
        float pcy = pr.x + 0.5f * ph, pcx = pr.y + 0.5f * pw;
        float d0 = dd.x * 0.1f, d1 = dd.y * 0.1f;
        float d2 = dd.z * 0.2f, d3 = dd.w * 0.2f;
        float cy = d0 * ph + pcy, cx = d1 * pw + pcx;
        float h = expf(d2) * ph, w = expf(d3) * pw;
        float4 bx;
        bx.x = fminf(fmaxf(cy - h * 0.5f, 0.f), 1.f);
        bx.y = fminf(fmaxf(cx - w * 0.5f, 0.f), 1.f);
        bx.z = fminf(fmaxf(cy + h * 0.5f, 0.f), 1.f);
        bx.w = fminf(fmaxf(cx + w * 0.5f, 0.f), 1.f);
        g_boxes[bBase + n] = bx;
    }

    uint32_t bar[2] = { smem_u32(&sBar[0]), smem_u32(&sBar[1]) };
    if (tid == 0) { mbar_init(bar[0], 1); mbar_init(bar[1], 1); }
    asm volatile("fence.proxy.async.shared::cta;" ::: "memory");
    __syncthreads();

    const float* gt0 = labels + (bBase + blk0) * (size_t)C;

    auto prefetch = [&](int t) {
        int naT = min(ATILE, nAll - t * ATILE);
        uint32_t bytes = (uint32_t)naT * C * 4u;
        const float* gsrc = gt0 + (size_t)t * ATILE * C;
        float* sdst = sL[t & 1];
        bool al = ((((uintptr_t)gsrc) & 15) == 0);
        uint32_t bb = al ? (bytes & ~15u) : 0u;
        if (tid == 0) {
            mbar_expect_tx(bar[t & 1], bb);
            if (bb) bulk_g2s(smem_u32(sdst), gsrc, bb, bar[t & 1]);
        }
        int remF = (int)((bytes - bb) >> 2);
        int baseF = (int)(bb >> 2);
        for (int i = tid; i < remF; i += 256) sdst[baseF + i] = gsrc[baseF + i];
    };

    prefetch(0);
    if (nt > 1) prefetch(1);
    __syncthreads();

    int a4 = tid >> 2;                 // anchor-in-tile 0..63
    int q  = tid & 3;                  // quarter within anchor
    int start = q * 20 + (q != 0);     // class range start: {0,21,41,61}
    int len   = (q == 0) ? 21 : 20;
    int laneBase = (tid & 31) & ~3;

    for (int t = 0; t < nt; t++) {
        mbar_wait(bar[t & 1], (t >> 1) & 1);

        const float* buf = sL[t & 1];
        int naT = min(ATILE, nAll - t * ATILE);
        bool valid = (a4 < naT);
        const float* row = buf + (valid ? a4 : 0) * C;

        float v0 = (q == 0) ? row[0] : -1e30f;
        float m = -1e30f;
        unsigned cb = 0;
        #pragma unroll
        for (int i = 0; i < 21; i++) {
            if (i < len) {
                int c = start + i;
                float v = row[c];
                m = fmaxf(m, (c == 0) ? -1e30f : v);
                float th = (c == 0) ? TH_C0 : TH_CX;   // per-class shortlist cut
                if (v > th) cb |= (1u << i);
            }
        }
        m = fmaxf(m, __shfl_xor_sync(0xffffffffu, m, 1));
        m = fmaxf(m, __shfl_xor_sync(0xffffffffu, m, 2));
        v0 = __shfl_sync(0xffffffffu, v0, laneBase);
        bool mask = (m > v0);          // argmax != 0 (first-index tie-break)

        if (valid) {
            int n = blk0 + t * ATILE + a4;
            if (q == 0) g_mask[bBase + n] = (unsigned char)mask;
            if (mask && cb) {
                unsigned tail = 0xFFFFFFFFu - (unsigned)n;
                while (cb) {
                    int k = __ffs(cb) - 1; cb &= cb - 1;
                    int c = start + k;
                    float v = row[c];
                    int col = b * C + c;
                    int p = atomicAdd(&g_candCnt[col], 1);
                    if (p < CAP)
                        g_cand[(size_t)col * CAP + p] =
                            ((ull)__float_as_uint(v) << 32) | (ull)tail;
                }
            }
        }
        __syncthreads();
        if (t + 2 < nt) prefetch(t + 2);
    }
}

// ---------------- warp-local NMS: load->reg-sort->gather->scan ----------------
// Returns kept count; writes g_keptScore/g_keptN for col.
template<int R>
__device__ __forceinline__ int warp_nms_run(
    const ull* __restrict__ gsrc, int cnt, size_t bBase, int lane, int col,
    float4* cboxW)
{
    ull v[R];
    #pragma unroll
    for (int r = 0; r < R; r++) {
        int i = r * 32 + lane;
        v[r] = (i < cnt) ? gsrc[i] : 0ull;
    }
    wsortN<R>(v, lane);

    // gather top GATHN boxes into per-warp smem
    #pragma unroll
    for (int r = 0; r < GATHN / 32; r++) {
        int i = r * 32 + lane;
        if (r < R && i < cnt) {
            unsigned nn = 0xFFFFFFFFu - (unsigned)(v[r] & 0xFFFFFFFFull);
            cboxW[i] = g_boxes[bBase + nn];
        }
    }
    __syncwarp();

    int m = min(cnt, R * 32);
    int kept = 0;
    float4 kb0 = make_float4(0, 0, 0, 0), kb1 = make_float4(0, 0, 0, 0);
    ull kq0 = 0, kq1 = 0;
    #pragma unroll
    for (int r = 0; r < R; r++) {
        if (r * 32 >= m || kept >= KPC) break;
        for (int e = 0; e < 32; e++) {
            int i = r * 32 + e;
            if (i >= m || kept >= KPC) break;
            ull kk = __shfl_sync(0xffffffffu, v[r], e);
            unsigned nn = 0xFFFFFFFFu - (unsigned)(kk & 0xFFFFFFFFull);
            float4 bb = (i < GATHN) ? cboxW[i] : g_boxes[bBase + nn];
            bool sup = false;
            if (lane < kept) sup = iouf(kb0, bb) > 0.5f;
            if (lane + 32 < kept) sup = sup || (iouf(kb1, bb) > 0.5f);
            if (!__any_sync(0xffffffffu, sup)) {
                if (lane == (kept & 31)) {
                    if (kept < 32) { kb0 = bb; kq0 = kk; }
                    else           { kb1 = bb; kq1 = kk; }
                }
                kept++;
            }
        }
    }

    // write out (lanes 0..31 -> slots 0..31; lanes 0..17 -> slots 32..49)
    float s0 = 0.f; int n0 = 0;
    if (lane < kept) {
        s0 = __uint_as_float((unsigned)(kq0 >> 32));
        n0 = (int)(0xFFFFFFFFu - (unsigned)(kq0 & 0xFFFFFFFFull));
    }
    g_keptScore[(size_t)col * KPC + lane] = s0;
    g_keptN   [(size_t)col * KPC + lane] = n0;
    if (lane < KPC - 32) {
        float s1 = 0.f; int n1 = 0;
        if (lane + 32 < kept) {
            s1 = __uint_as_float((unsigned)(kq1 >> 32));
            n1 = (int)(0xFFFFFFFFu - (unsigned)(kq1 & 0xFFFFFFFFull));
        }
        g_keptScore[(size_t)col * KPC + 32 + lane] = s1;
        g_keptN   [(size_t)col * KPC + 32 + lane] = n1;
    }
    return kept;
}

// ---------------- Phase B: warp-per-class NMS + fused per-batch merge ----------
__global__ __launch_bounds__(128) void phaseB(
    const float* __restrict__ labels, float* __restrict__ out,
    int B, int N, int C, int BPB)
{
    __shared__ __align__(16) float4 sCbox[4][GATHN];   // 6 KB
    __shared__ ull sSel[SELB];                          // 4 KB (merge / t3 reuse)
    __shared__ int sHist[NBIN];                         // 2 KB
    __shared__ float4 keptBox[KPC];
    __shared__ float keptS[KPC];
    __shared__ int keptNi[KPC];
    __shared__ int s_fb[4];
    __shared__ int s_elect, s_kept;
    __shared__ ull s_wmax[4];
    __shared__ ull s_best;

    int tid = threadIdx.x, lane = tid & 31, wid = tid >> 5;
    int blk = blockIdx.x;
    int b = blk / BPB;
    int cBase = (blk - b * BPB) * 4;
    int c = cBase + wid;
    size_t bBase = (size_t)b * N;
    bool active = (c < C);
    int col = b * C + (active ? c : 0);

    int fb = 0;
    if (active) {
        int rawCnt = g_candCnt[col];
        if (lane == 0) g_candCnt[col] = 0;          // reset for next replay
        int cnt = min(rawCnt, CAP);
        const ull* gsrc = g_cand + (size_t)col * CAP;
        int kept = 0;
        if (rawCnt > CAP)      fb = 1;
        else if (cnt <= 256)   kept = warp_nms_run<8>(gsrc, cnt, bBase, lane, col, sCbox[wid]);
        else if (cnt <= 512)   kept = warp_nms_run<16>(gsrc, cnt, bBase, lane, col, sCbox[wid]);
        else                   fb = 1;
        if (!fb && kept < KPC) fb = 1;               // shortlist insufficient
    }
    if (lane == 0) s_fb[wid] = active ? fb : 0;
    __syncthreads();

    // ---- tier-3 exact repeated-argmax greedy (block-wide; never taken in practice)
    for (int w = 0; w < 4; w++) {
        if (!s_fb[w]) continue;
        int cc = cBase + w;
        int col3 = b * C + cc;
        if (tid == 0) s_kept = 0;
        __syncthreads();
        for (int iter = 0; iter < KPC; iter++) {
            int kept = s_kept;
            ull best = 0ull;
            for (int n = tid; n < N; n += 128) {
                if (!g_mask[bBase + n]) continue;
                float s = labels[(bBase + n) * C + cc];
                if (s <= 0.5f) continue;
                ull key = ((ull)__float_as_uint(s) << 32) |
                          (0xFFFFFFFFu - (unsigned)n);
                if (key <= best) continue;
                float4 bb = g_boxes[bBase + n];
                bool sup = false;
                for (int t = 0; t < kept && !sup; t++) {
                    if (keptNi[t] == n) sup = true;
                    else if (iouf(keptBox[t], bb) > 0.5f) sup = true;
                }
                if (!sup) best = key;
            }
            for (int off = 16; off; off >>= 1) {
                ull o = __shfl_xor_sync(0xffffffffu, best, off);
                if (o > best) best = o;
            }
            if (lane == 0) s_wmax[wid] = best;
            __syncthreads();
            if (wid == 0) {
                ull vv = (lane < 4) ? s_wmax[lane] : 0ull;
                for (int off = 2; off; off >>= 1) {
                    ull o = __shfl_xor_sync(0xffffffffu, vv, off);
                    if (o > vv) vv = o;
                }
                if (lane == 0) s_best = vv;
            }
            __syncthreads();
            if (s_best == 0ull) break;
            if (tid == 0) {
                ull kk = s_best;
                unsigned nn = 0xFFFFFFFFu - (unsigned)(kk & 0xFFFFFFFFull);
                keptBox[s_kept] = g_boxes[bBase + nn];
                keptS[s_kept] = __uint_as_float((unsigned)(kk >> 32));
                keptNi[s_kept] = (int)nn;
                s_kept = s_kept + 1;
            }
            __syncthreads();
        }
        __syncthreads();
        int kept = s_kept;
        for (int k2 = tid; k2 < KPC; k2 += 128) {
            g_keptScore[(size_t)col3 * KPC + k2] = (k2 < kept) ? keptS[k2] : 0.f;
            g_keptN   [(size_t)col3 * KPC + k2] = (k2 < kept) ? keptNi[k2] : 0;
        }
        __syncthreads();
    }

    // ================= fused per-batch merge (last block of batch b) ==========
    __threadfence();
    __syncthreads();
    if (tid == 0) {
        int old = atomicAdd(&g_done[b], 1);
        s_elect = (old == BPB - 1);
        if (s_elect) g_done[b] = 0;          // reset for next replay
    }
    __syncthreads();
    if (!s_elect) return;
    __threadfence();                          // acquire all blocks' results

    int M = C * KPC;                           // 4050
    const float* ks = g_keptScore + (size_t)b * M;
    __shared__ int s_cnt2, s_thr, s_fbm, s_vc;

    for (int i = tid; i < NBIN; i += 128) sHist[i] = 0;
    if (tid == 0) { s_cnt2 = 0; s_thr = -1; s_fbm = 0; s_vc = 0; }
    __syncthreads();

    const unsigned LOu = __float_as_uint(0.9975f);
    for (int i = tid; i < M; i += 128) {
        unsigned fbits = __float_as_uint(ks[i]);
        int d = (int)(fbits - LOu);
        int bin = (d < 0) ? 0 : min(NBIN - 1, d >> 7);
        atomicAdd(&sHist[bin], 1);
    }
    __syncthreads();

    for (int off = 1; off < NBIN; off <<= 1) {
        int v[4];
        #pragma unroll
        for (int r = 0; r < 4; r++) {
            int i = tid + 128 * r;
            v[r] = sHist[i] + ((i + off < NBIN) ? sHist[i + off] : 0);
        }
        __syncthreads();
        #pragma unroll
        for (int r = 0; r < 4; r++) sHist[tid + 128 * r] = v[r];
        __syncthreads();
    }
    for (int t = tid; t < NBIN; t += 128)
        if (sHist[t] >= MAXTOT && (t == NBIN - 1 || sHist[t + 1] < MAXTOT)) s_thr = t;
    __syncthreads();
    int thr = s_thr;
    if (tid == 0 && (thr <= 0 || sHist[thr] > SELB)) s_fbm = 1;
    __syncthreads();

    if (!s_fbm) {
        for (int i = tid; i < M; i += 128) {
            unsigned fbits = __float_as_uint(ks[i]);
            int d = (int)(fbits - LOu);
            int bin = (d < 0) ? 0 : min(NBIN - 1, d >> 7);
            if (bin >= thr) {
                int p = atomicAdd(&s_cnt2, 1);
                if (p < SELB)
                    sSel[p] = ((ull)fbits << 32) | (0xFFFFFFFFu - (unsigned)i);
            }
        }
        __syncthreads();
        int nsel = s_cnt2;
        for (int i = tid; i < SELB; i += 128)
            if (i >= nsel) sSel[i] = 0ull;
        __syncthreads();
        bitonic_desc(sSel, SELB, tid, 128);
    } else {
        // exact fallback: 200 sequential argmax passes (never taken)
        __shared__ ull s_last;
        if (tid == 0) s_last = ~0ull;
        __syncthreads();
        for (int it = 0; it < MAXTOT; it++) {
            ull lim = s_last;
            ull best = 0ull;
            for (int i = tid; i < M; i += 128) {
                ull key = ((ull)__float_as_uint(ks[i]) << 32) |
                          (0xFFFFFFFFu - (unsigned)i);
                if (key < lim && key > best) best = key;
            }
            for (int off = 16; off; off >>= 1) {
                ull o = __shfl_xor_sync(0xffffffffu, best, off);
                if (o > best) best = o;
            }
            if (lane == 0) s_wmax[wid] = best;
            __syncthreads();
            if (wid == 0) {
                ull vv = (lane < 4) ? s_wmax[lane] : 0ull;
                for (int off = 2; off; off >>= 1) {
                    ull o = __shfl_xor_sync(0xffffffffu, vv, off);
                    if (o > vv) vv = o;
                }
                if (lane == 0) { sSel[it] = vv; s_last = vv; }
            }
            __syncthreads();
        }
    }

    float* outBoxes   = out;
    float* outScores  = out + (size_t)B * MAXTOT * 4;
    float* outClasses = outScores + (size_t)B * MAXTOT;
    float* outCount   = outClasses + (size_t)B * MAXTOT;

    for (int i = tid; i < MAXTOT; i += 128) {
        ull kk = sSel[i];
        float s = __uint_as_float((unsigned)(kk >> 32));
        unsigned flat = 0xFFFFFFFFu - (unsigned)(kk & 0xFFFFFFFFull);
        float4 bx = make_float4(0.f, 0.f, 0.f, 0.f);
        float cls = 0.f;
        if (s > 0.f) {
            int n = g_keptN[(size_t)b * M + flat];
            bx = g_boxes[bBase + n];
            cls = (float)(flat / KPC);
            atomicAdd(&s_vc, 1);
        }
        size_t o = (size_t)b * MAXTOT + i;
        outBoxes[o * 4 + 0] = bx.x;
        outBoxes[o * 4 + 1] = bx.y;
        outBoxes[o * 4 + 2] = bx.z;
        outBoxes[o * 4 + 3] = bx.w;
        outScores[o]  = s;
        outClasses[o] = cls;
    }
    __syncthreads();
    if (tid == 0) outCount[b] = (float)s_vc;
}

// ---------------- launch ----------------
extern "C" void kernel_launch(void* const* d_in, const int* in_sizes, int n_in,
                              void* d_out, int out_size) {
    const float* deltas = (const float*)d_in[0];   // pred_deltas (B,N,4)
    const float* labels = (const float*)d_in[1];   // pred_labels (B,N,C)
    const float* priors = (const float*)d_in[2];   // prior_boxes (N,4)

    int N = in_sizes[2] / 4;
    int B = in_sizes[0] / (4 * N);
    int C = in_sizes[1] / (B * N);
    int BPB = (C + 3) / 4;                          // blocks per batch in phaseB

    dim3 gA((N + ATILE * ANIT - 1) / (ATILE * ANIT), B);
    phaseA<<<gA, 256>>>(labels, deltas, priors, N, C);
    phaseB<<<B * BPB, 128>>>(labels, (float*)d_out, B, N, C, BPB);
}

// round 12
// speedup vs baseline: 1.3540x; 1.0190x over previous
#include <cuda_runtime.h>
#include <cstdint>

#define MAXB 16
#define MAXN 24564
#define MAXC 81
#define CAP  1024      // per-(b,c) candidate shortlist capacity
#define KPC  50        // MAX_PER_CLASS
#define MAXTOT 200
#define TH_C0 0.98f    // shortlist threshold, class 0
#define TH_CX 0.995f   // shortlist threshold, classes != 0
#define SELB  512
#define NBIN  512
#define ATILE 64       // anchors per phaseA pipeline stage
#define ANIT  8        // tiles per phaseA block
#define GATHN 96       // boxes prefetched to smem per class

typedef unsigned long long ull;

// ---------------- static device scratch ----------------
__device__ float4 g_boxes[MAXB * MAXN];
__device__ unsigned char g_mask[MAXB * MAXN];
__device__ ull g_cand[(size_t)MAXB * MAXC * CAP];
__device__ int g_candCnt[MAXB * MAXC];
__device__ float g_keptScore[MAXB * MAXC * KPC];
__device__ int   g_keptN[MAXB * MAXC * KPC];
__device__ int   g_done[MAXB];          // zero-initialized at module load

__device__ __forceinline__ float iouf(float4 a, float4 b) {
    float iy1 = fmaxf(a.x, b.x);
    float ix1 = fmaxf(a.y, b.y);
    float iy2 = fminf(a.z, b.z);
    float ix2 = fminf(a.w, b.w);
    float inter = fmaxf(iy2 - iy1, 0.f) * fmaxf(ix2 - ix1, 0.f);
    float a0 = (a.z - a.x) * (a.w - a.y);
    float a1 = (b.z - b.x) * (b.w - b.y);
    return inter / (a0 + a1 - inter + 1e-8f);
}

__device__ __forceinline__ void bitonic_desc(ull* a, int P, int tid, int nthreads) {
    for (int k = 2; k <= P; k <<= 1) {
        for (int j = k >> 1; j > 0; j >>= 1) {
            for (int i = tid; i < P; i += nthreads) {
                int ixj = i ^ j;
                if (ixj > i) {
                    ull x = a[i], y = a[ixj];
                    if (((i & k) != 0) ? (x > y) : (x < y)) { a[i] = y; a[ixj] = x; }
                }
            }
            __syncthreads();
        }
    }
}

// ---- register bitonic stages (compile-time indices only) ----
template<int R, int RJ>
__device__ __forceinline__ void regstage(ull* v, int lane, int k) {
    #pragma unroll
    for (int r = 0; r < R; r++) {
        if ((r & RJ) == 0) {
            int rh = r | RJ;
            int idx = r * 32 + lane;
            bool dir = ((idx & k) == 0);
            ull a = v[r], b = v[rh];
            ull mx = a > b ? a : b;
            ull mn = a > b ? b : a;
            v[r]  = dir ? mx : mn;
            v[rh] = dir ? mn : mx;
        }
    }
}

template<int R>
__device__ __forceinline__ void wsortN(ull* v, int lane) {
    const int n = R * 32;
    for (int k = 2; k <= n; k <<= 1) {
        for (int j = k >> 1; j > 0; j >>= 1) {
            if (j >= 32) {
                switch (j >> 5) {
                    case 1: regstage<R, 1>(v, lane, k); break;
                    case 2: regstage<R, 2>(v, lane, k); break;
                    case 4: regstage<R, 4>(v, lane, k); break;
                    case 8: regstage<R, 8>(v, lane, k); break;
                }
            } else {
                #pragma unroll
                for (int r = 0; r < R; r++) {
                    int idx = r * 32 + lane;
                    ull o = __shfl_xor_sync(0xffffffffu, v[r], j);
                    bool dir = ((idx & k) == 0);
                    bool lower = ((lane & j) == 0);
                    ull mx = v[r] > o ? v[r] : o;
                    ull mn = v[r] > o ? o : v[r];
                    v[r] = (dir == lower) ? mx : mn;
                }
            }
        }
    }
}

// ---- async-copy helpers ----
__device__ __forceinline__ uint32_t smem_u32(const void* p) {
    return (uint32_t)__cvta_generic_to_shared(p);
}
__device__ __forceinline__ void mbar_init(uint32_t a, uint32_t cnt) {
    asm volatile("mbarrier.init.shared.b64 [%0], %1;" :: "r"(a), "r"(cnt) : "memory");
}
__device__ __forceinline__ void mbar_expect_tx(uint32_t a, uint32_t bytes) {
    asm volatile("mbarrier.arrive.expect_tx.shared.b64 _, [%0], %1;"
                 :: "r"(a), "r"(bytes) : "memory");
}
__device__ __forceinline__ void bulk_g2s(uint32_t sdst, const void* gsrc,
                                         uint32_t bytes, uint32_t mbar) {
    asm volatile(
        "cp.async.bulk.shared::cluster.global.mbarrier::complete_tx::bytes "
        "[%0], [%1], %2, [%3];"
        :: "r"(sdst), "l"(gsrc), "r"(bytes), "r"(mbar) : "memory");
}
__device__ __forceinline__ void mbar_wait(uint32_t a, uint32_t parity) {
    asm volatile(
        "{\n\t.reg .pred p;\n\t"
        "W%=:\n\t"
        "mbarrier.try_wait.parity.acquire.cta.shared::cta.b64 p, [%0], %1, 0x989680;\n\t"
        "@!p bra W%=;\n\t}"
        :: "r"(a), "r"(parity) : "memory");
}

// ---------------- Phase A: bulk-copy pipeline, 4 lanes per anchor --------------
__global__ __launch_bounds__(256) void phaseA(
    const float* __restrict__ labels,   // (B,N,C)
    const float* __restrict__ deltas,   // (B,N,4)
    const float* __restrict__ priors,   // (N,4)
    int N, int C)
{
    __shared__ __align__(16) float sL[2][ATILE * MAXC];   // 2 x 20.7 KB
    __shared__ __align__(8) ull sBar[2];

    int tid = threadIdx.x;
    int b = blockIdx.y;
    int blk0 = blockIdx.x * (ATILE * ANIT);
    int nAll = min(ATILE * ANIT, N - blk0);
    if (nAll <= 0) return;
    int nt = (nAll + ATILE - 1) / ATILE;
    size_t bBase = (size_t)b * N;

    for (int i = tid; i < nAll; i += 256) {
        int n = blk0 + i;
        float4 pr = ((const float4*)priors)[n];
        float4 dd = ((const float4*)deltas)[bBase + n];
        float ph = pr.z - pr.x, pw = pr.w - pr.y;
        float pcy = pr.x + 0.5f * ph, pcx = pr.y + 0.5f * pw;
        float d0 = dd.x * 0.1f, d1 = dd.y * 0.1f;
        float d2 = dd.z * 0.2f, d3 = dd.w * 0.2f;
        float cy = d0 * ph + pcy, cx = d1 * pw + pcx;
        float h = expf(d2) * ph, w = expf(d3) * pw;
        float4 bx;
        bx.x = fminf(fmaxf(cy - h * 0.5f, 0.f), 1.f);
        bx.y = fminf(fmaxf(cx - w * 0.5f, 0.f), 1.f);
        bx.z = fminf(fmaxf(cy + h * 0.5f, 0.f), 1.f);
        bx.w = fminf(fmaxf(cx + w * 0.5f, 0.f), 1.f);
        g_boxes[bBase + n] = bx;
    }

    uint32_t bar[2] = { smem_u32(&sBar[0]), smem_u32(&sBar[1]) };
    if (tid == 0) { mbar_init(bar[0], 1); mbar_init(bar[1], 1); }
    asm volatile("fence.proxy.async.shared::cta;" ::: "memory");
    __syncthreads();

    const float* gt0 = labels + (bBase + blk0) * (size_t)C;

    auto prefetch = [&](int t) {
        int naT = min(ATILE, nAll - t * ATILE);
        uint32_t bytes = (uint32_t)naT * C * 4u;
        const float* gsrc = gt0 + (size_t)t * ATILE * C;
        float* sdst = sL[t & 1];
        bool al = ((((uintptr_t)gsrc) & 15) == 0);
        uint32_t bb = al ? (bytes & ~15u) : 0u;
        if (tid == 0) {
            mbar_expect_tx(bar[t & 1], bb);
            if (bb) bulk_g2s(smem_u32(sdst), gsrc, bb, bar[t & 1]);
        }
        int remF = (int)((bytes - bb) >> 2);
        int baseF = (int)(bb >> 2);
        for (int i = tid; i < remF; i += 256) sdst[baseF + i] = gsrc[baseF + i];
    };

    prefetch(0);
    if (nt > 1) prefetch(1);
    __syncthreads();

    int a4 = tid >> 2;
    int q  = tid & 3;
    int start = q * 20 + (q != 0);
    int len   = (q == 0) ? 21 : 20;
    int laneBase = (tid & 31) & ~3;

    for (int t = 0; t < nt; t++) {
        mbar_wait(bar[t & 1], (t >> 1) & 1);

        const float* buf = sL[t & 1];
        int naT = min(ATILE, nAll - t * ATILE);
        bool valid = (a4 < naT);
        const float* row = buf + (valid ? a4 : 0) * C;

        float v0 = (q == 0) ? row[0] : -1e30f;
        float m = -1e30f;
        unsigned cb = 0;
        #pragma unroll
        for (int i = 0; i < 21; i++) {
            if (i < len) {
                int c = start + i;
                float v = row[c];
                m = fmaxf(m, (c == 0) ? -1e30f : v);
                float th = (c == 0) ? TH_C0 : TH_CX;
                if (v > th) cb |= (1u << i);
            }
        }
        m = fmaxf(m, __shfl_xor_sync(0xffffffffu, m, 1));
        m = fmaxf(m, __shfl_xor_sync(0xffffffffu, m, 2));
        v0 = __shfl_sync(0xffffffffu, v0, laneBase);
        bool mask = (m > v0);

        if (valid) {
            int n = blk0 + t * ATILE + a4;
            if (q == 0) g_mask[bBase + n] = (unsigned char)mask;
            if (mask && cb) {
                unsigned tail = 0xFFFFFFFFu - (unsigned)n;
                while (cb) {
                    int k = __ffs(cb) - 1; cb &= cb - 1;
                    int c = start + k;
                    float v = row[c];
                    int col = b * C + c;
                    int p = atomicAdd(&g_candCnt[col], 1);
                    if (p < CAP)
                        g_cand[(size_t)col * CAP + p] =
                            ((ull)__float_as_uint(v) << 32) | (ull)tail;
                }
            }
        }
        __syncthreads();
        if (t + 2 < nt) prefetch(t + 2);
    }
}

// ---------------- warp-local NMS: load->reg-sort->smem->scan ------------------
// Sorted keys land in per-warp smem; the scan reads smem only (no dynamic
// register indexing, no per-candidate shuffles). Returns kept count.
template<int R>
__device__ __forceinline__ int warp_nms_run(
    const ull* __restrict__ gsrc, int cnt, size_t bBase, int lane, int col,
    float4* cboxW, ull* sortW)
{
    ull v[R];
    #pragma unroll
    for (int r = 0; r < R; r++) {
        int i = r * 32 + lane;
        v[r] = (i < cnt) ? gsrc[i] : 0ull;
    }
    wsortN<R>(v, lane);
    #pragma unroll
    for (int r = 0; r < R; r++) sortW[r * 32 + lane] = v[r];
    __syncwarp();

    int m = min(cnt, R * 32);

    // gather top boxes into per-warp smem
    for (int i = lane; i < GATHN && i < m; i += 32) {
        unsigned nn = 0xFFFFFFFFu - (unsigned)(sortW[i] & 0xFFFFFFFFull);
        cboxW[i] = g_boxes[bBase + nn];
    }
    __syncwarp();

    // sequential scan; kept boxes live in lane registers (lane l owns slots l, l+32)
    int kept = 0;
    float4 kb0 = make_float4(0, 0, 0, 0), kb1 = make_float4(0, 0, 0, 0);
    ull kq0 = 0, kq1 = 0;
    for (int i = 0; i < m && kept < KPC; i++) {
        ull kk = sortW[i];                 // uniform LDS broadcast
        unsigned nn = 0xFFFFFFFFu - (unsigned)(kk & 0xFFFFFFFFull);
        float4 bb = (i < GATHN) ? cboxW[i] : g_boxes[bBase + nn];
        bool sup = false;
        if (lane < kept) sup = iouf(kb0, bb) > 0.5f;
        if (lane + 32 < kept) sup = sup || (iouf(kb1, bb) > 0.5f);
        if (!__any_sync(0xffffffffu, sup)) {
            if (lane == (kept & 31)) {
                if (kept < 32) { kb0 = bb; kq0 = kk; }
                else           { kb1 = bb; kq1 = kk; }
            }
            kept++;
        }
    }

    float s0 = 0.f; int n0 = 0;
    if (lane < kept) {
        s0 = __uint_as_float((unsigned)(kq0 >> 32));
        n0 = (int)(0xFFFFFFFFu - (unsigned)(kq0 & 0xFFFFFFFFull));
    }
    g_keptScore[(size_t)col * KPC + lane] = s0;
    g_keptN   [(size_t)col * KPC + lane] = n0;
    if (lane < KPC - 32) {
        float s1 = 0.f; int n1 = 0;
        if (lane + 32 < kept) {
            s1 = __uint_as_float((unsigned)(kq1 >> 32));
            n1 = (int)(0xFFFFFFFFu - (unsigned)(kq1 & 0xFFFFFFFFull));
        }
        g_keptScore[(size_t)col * KPC + 32 + lane] = s1;
        g_keptN   [(size_t)col * KPC + 32 + lane] = n1;
    }
    return kept;
}

// ---------------- Phase B: warp-per-class NMS + fused per-batch merge ----------
__global__ __launch_bounds__(128) void phaseB(
    const float* __restrict__ labels, float* __restrict__ out,
    int B, int N, int C, int BPB)
{
    __shared__ __align__(16) float4 sCbox[4][GATHN];   // 6 KB
    __shared__ __align__(16) ull sSort[4][SELB];       // 16 KB per-warp sorted keys
    __shared__ ull sSel[SELB];                          // 4 KB (merge / t3 reuse)
    __shared__ int sHist[NBIN];                         // 2 KB
    __shared__ float4 keptBox[KPC];
    __shared__ float keptS[KPC];
    __shared__ int keptNi[KPC];
    __shared__ int s_fb[4];
    __shared__ int s_elect, s_kept;
    __shared__ ull s_wmax[4];
    __shared__ ull s_best;

    int tid = threadIdx.x, lane = tid & 31, wid = tid >> 5;
    int blk = blockIdx.x;
    int b = blk / BPB;
    int cBase = (blk - b * BPB) * 4;
    int c = cBase + wid;
    size_t bBase = (size_t)b * N;
    bool active = (c < C);
    int col = b * C + (active ? c : 0);

    int fb = 0;
    if (active) {
        int rawCnt = g_candCnt[col];
        if (lane == 0) g_candCnt[col] = 0;          // reset for next replay
        int cnt = min(rawCnt, CAP);
        const ull* gsrc = g_cand + (size_t)col * CAP;
        int kept = 0;
        if (rawCnt > CAP)      fb = 1;
        else if (cnt <= 128)   kept = warp_nms_run<4>(gsrc, cnt, bBase, lane, col, sCbox[wid], sSort[wid]);
        else if (cnt <= 256)   kept = warp_nms_run<8>(gsrc, cnt, bBase, lane, col, sCbox[wid], sSort[wid]);
        else if (cnt <= 512)   kept = warp_nms_run<16>(gsrc, cnt, bBase, lane, col, sCbox[wid], sSort[wid]);
        else                   fb = 1;
        if (!fb && kept < KPC) fb = 1;               // shortlist insufficient
    }
    if (lane == 0) s_fb[wid] = active ? fb : 0;
    __syncthreads();

    // ---- tier-3 exact repeated-argmax greedy (block-wide; never taken in practice)
    for (int w = 0; w < 4; w++) {
        if (!s_fb[w]) continue;
        int cc = cBase + w;
        int col3 = b * C + cc;
        if (tid == 0) s_kept = 0;
        __syncthreads();
        for (int iter = 0; iter < KPC; iter++) {
            int kept = s_kept;
            ull best = 0ull;
            for (int n = tid; n < N; n += 128) {
                if (!g_mask[bBase + n]) continue;
                float s = labels[(bBase + n) * C + cc];
                if (s <= 0.5f) continue;
                ull key = ((ull)__float_as_uint(s) << 32) |
                          (0xFFFFFFFFu - (unsigned)n);
                if (key <= best) continue;
                float4 bb = g_boxes[bBase + n];
                bool sup = false;
                for (int t = 0; t < kept && !sup; t++) {
                    if (keptNi[t] == n) sup = true;
                    else if (iouf(keptBox[t], bb) > 0.5f) sup = true;
                }
                if (!sup) best = key;
            }
            for (int off = 16; off; off >>= 1) {
                ull o = __shfl_xor_sync(0xffffffffu, best, off);
                if (o > best) best = o;
            }
            if (lane == 0) s_wmax[wid] = best;
            __syncthreads();
            if (wid == 0) {
                ull vv = (lane < 4) ? s_wmax[lane] : 0ull;
                for (int off = 2; off; off >>= 1) {
                    ull o = __shfl_xor_sync(0xffffffffu, vv, off);
                    if (o > vv) vv = o;
                }
                if (lane == 0) s_best = vv;
            }
            __syncthreads();
            if (s_best == 0ull) break;
            if (tid == 0) {
                ull kk = s_best;
                unsigned nn = 0xFFFFFFFFu - (unsigned)(kk & 0xFFFFFFFFull);
                keptBox[s_kept] = g_boxes[bBase + nn];
                keptS[s_kept] = __uint_as_float((unsigned)(kk >> 32));
                keptNi[s_kept] = (int)nn;
                s_kept = s_kept + 1;
            }
            __syncthreads();
        }
        __syncthreads();
        int kept = s_kept;
        for (int k2 = tid; k2 < KPC; k2 += 128) {
            g_keptScore[(size_t)col3 * KPC + k2] = (k2 < kept) ? keptS[k2] : 0.f;
            g_keptN   [(size_t)col3 * KPC + k2] = (k2 < kept) ? keptNi[k2] : 0;
        }
        __syncthreads();
    }

    // ================= fused per-batch merge (last block of batch b) ==========
    __threadfence();
    __syncthreads();
    if (tid == 0) {
        int old = atomicAdd(&g_done[b], 1);
        s_elect = (old == BPB - 1);
        if (s_elect) g_done[b] = 0;
    }
    __syncthreads();
    if (!s_elect) return;
    __threadfence();

    int M = C * KPC;                           // 4050
    const float* ks = g_keptScore + (size_t)b * M;
    __shared__ int s_cnt2, s_thr, s_fbm, s_vc;

    for (int i = tid; i < NBIN; i += 128) sHist[i] = 0;
    if (tid == 0) { s_cnt2 = 0; s_thr = -1; s_fbm = 0; s_vc = 0; }
    __syncthreads();

    const unsigned LOu = __float_as_uint(0.9975f);
    for (int i = tid; i < M; i += 128) {
        unsigned fbits = __float_as_uint(ks[i]);
        int d = (int)(fbits - LOu);
        int bin = (d < 0) ? 0 : min(NBIN - 1, d >> 7);
        atomicAdd(&sHist[bin], 1);
    }
    __syncthreads();

    for (int off = 1; off < NBIN; off <<= 1) {
        int v[4];
        #pragma unroll
        for (int r = 0; r < 4; r++) {
            int i = tid + 128 * r;
            v[r] = sHist[i] + ((i + off < NBIN) ? sHist[i + off] : 0);
        }
        __syncthreads();
        #pragma unroll
        for (int r = 0; r < 4; r++) sHist[tid + 128 * r] = v[r];
        __syncthreads();
    }
    for (int t = tid; t < NBIN; t += 128)
        if (sHist[t] >= MAXTOT && (t == NBIN - 1 || sHist[t + 1] < MAXTOT)) s_thr = t;
    __syncthreads();
    int thr = s_thr;
    if (tid == 0 && (thr <= 0 || sHist[thr] > SELB)) s_fbm = 1;
    __syncthreads();

    if (!s_fbm) {
        for (int i = tid; i < M; i += 128) {
            unsigned fbits = __float_as_uint(ks[i]);
            int d = (int)(fbits - LOu);
            int bin = (d < 0) ? 0 : min(NBIN - 1, d >> 7);
            if (bin >= thr) {
                int p = atomicAdd(&s_cnt2, 1);
                if (p < SELB)
                    sSel[p] = ((ull)fbits << 32) | (0xFFFFFFFFu - (unsigned)i);
            }
        }
        __syncthreads();
        int nsel = s_cnt2;
        for (int i = tid; i < SELB; i += 128)
            if (i >= nsel) sSel[i] = 0ull;
        __syncthreads();
        bitonic_desc(sSel, SELB, tid, 128);
    } else {
        __shared__ ull s_last;
        if (tid == 0) s_last = ~0ull;
        __syncthreads();
        for (int it = 0; it < MAXTOT; it++) {
            ull lim = s_last;
            ull best = 0ull;
            for (int i = tid; i < M; i += 128) {
                ull key = ((ull)__float_as_uint(ks[i]) << 32) |
                          (0xFFFFFFFFu - (unsigned)i);
                if (key < lim && key > best) best = key;
            }
            for (int off = 16; off; off >>= 1) {
                ull o = __shfl_xor_sync(0xffffffffu, best, off);
                if (o > best) best = o;
            }
            if (lane == 0) s_wmax[wid] = best;
            __syncthreads();
            if (wid == 0) {
                ull vv = (lane < 4) ? s_wmax[lane] : 0ull;
                for (int off = 2; off; off >>= 1) {
                    ull o = __shfl_xor_sync(0xffffffffu, vv, off);
                    if (o > vv) vv = o;
                }
                if (lane == 0) { sSel[it] = vv; s_last = vv; }
            }
            __syncthreads();
        }
    }

    float* outBoxes   = out;
    float* outScores  = out + (size_t)B * MAXTOT * 4;
    float* outClasses = outScores + (size_t)B * MAXTOT;
    float* outCount   = outClasses + (size_t)B * MAXTOT;

    for (int i = tid; i < MAXTOT; i += 128) {
        ull kk = sSel[i];
        float s = __uint_as_float((unsigned)(kk >> 32));
        unsigned flat = 0xFFFFFFFFu - (unsigned)(kk & 0xFFFFFFFFull);
        float4 bx = make_float4(0.f, 0.f, 0.f, 0.f);
        float cls = 0.f;
        if (s > 0.f) {
            int n = g_keptN[(size_t)b * M + flat];
            bx = g_boxes[bBase + n];
            cls = (float)(flat / KPC);
            atomicAdd(&s_vc, 1);
        }
        size_t o = (size_t)b * MAXTOT + i;
        outBoxes[o * 4 + 0] = bx.x;
        outBoxes[o * 4 + 1] = bx.y;
        outBoxes[o * 4 + 2] = bx.z;
        outBoxes[o * 4 + 3] = bx.w;
        outScores[o]  = s;
        outClasses[o] = cls;
    }
    __syncthreads();
    if (tid == 0) outCount[b] = (float)s_vc;
}

// ---------------- launch ----------------
extern "C" void kernel_launch(void* const* d_in, const int* in_sizes, int n_in,
                              void* d_out, int out_size) {
    const float* deltas = (const float*)d_in[0];   // pred_deltas (B,N,4)
    const float* labels = (const float*)d_in[1];   // pred_labels (B,N,C)
    const float* priors = (const float*)d_in[2];   // prior_boxes (N,4)

    int N = in_sizes[2] / 4;
    int B = in_sizes[0] / (4 * N);
    int C = in_sizes[1] / (B * N);
    int BPB = (C + 3) / 4;                          // blocks per batch in phaseB

    dim3 gA((N + ATILE * ANIT - 1) / (ATILE * ANIT), B);
    phaseA<<<gA, 256>>>(labels, deltas, priors, N, C);
    phaseB<<<B * BPB, 128>>>(labels, (float*)d_out, B, N, C, BPB);
}